// round 4
// baseline (speedup 1.0000x reference)
#include <cuda_runtime.h>

// DTM (distance-to-measure) on a 64x64 integer grid.
// Per (b,c) slice: bound = 0.05 * sum(w). Per point p: walk grid points in
// order of increasing squared distance, accumulate weight until crossing
// bound, output sqrt((sum_{d<d*} d^2 w + d*^2 (bound - cum_before)) / bound).
// Order within equal-d^2 groups is irrelevant (value is order-invariant),
// so a lexicographic tie rank matches the reference top_k result.

#define HW 4096
#define NSLICE 12
#define NOFF 16129            // (dy,dx) in [-63,63]^2
#define NPAD 16256            // multiple of 128 (127 batches)
#define PITCH 65
#define ZSLOT (64 * PITCH)    // guaranteed-zero smem slot for OOB entries

// entry: .x = (dy*65+dx)<<16 | (dy+64)<<8 | (dx+64);  .y = float(d2) bits
__device__ __align__(16) uint2 g_tab[NPAD];

// ---- build: each offset computes its sorted rank in closed form ----

__global__ void __launch_bounds__(256) k_build() {
    int i = blockIdx.x * 256 + threadIdx.x;
    if (i >= NPAD) return;
    if (i >= NOFF) { g_tab[i] = make_uint2(0u, 0u); return; }
    int dy = i / 127 - 63;
    int dx = i % 127 - 63;
    int d2 = dy * dy + dx * dx;
    int pos = 0;
    for (int a = 0; a <= 63; a++) {       // +-a handled together
        int na = d2 - a * a;
        if (na < 0) break;
        int s = (int)sqrtf((float)na);    // exact floor here (see margin arg)
        bool perf = (s * s == na);
        if (na > 0) {                     // # of b with b^2 < na, |b|<=63
            int tt = perf ? s - 1 : s;
            if (tt > 63) tt = 63;
            int cb = 2 * tt + 1;
            pos += (a == 0) ? cb : 2 * cb;
        }
        if (perf && s <= 63) {            // ties b = +-s, lex (a,b) order
            if (a < dy) pos += (s == 0) ? 1 : 2;
            else if (a == dy) {
                if (-s < dx) pos++;
                if (s != 0 && s < dx) pos++;
            }
            if (a != 0) {
                int aa = -a;
                if (aa < dy) pos += (s == 0) ? 1 : 2;
                else if (aa == dy) {
                    if (-s < dx) pos++;
                    if (s != 0 && s < dx) pos++;
                }
            }
        }
    }
    int off = dy * PITCH + dx;
    unsigned vp = ((unsigned)(dy + 64) << 8) | (unsigned)(dx + 64);
    g_tab[pos] = make_uint2(((unsigned)(off & 0xFFFF) << 16) | vp,
                            __float_as_uint((float)d2));
}

// ---- main: one warp per point, 128 sorted entries per step (4/lane) ----

__global__ void __launch_bounds__(512, 2)
k_main(const float* __restrict__ x, float* __restrict__ out) {
    __shared__ float sw[ZSLOT + 1];
    __shared__ float sred[16];
    __shared__ float sbound;

    int t = threadIdx.x;
    int slice = blockIdx.x >> 8;   // 256 point-groups of 16 per slice
    int pg = blockIdx.x & 255;
    const float* src = x + slice * HW;

    if (t == 0) sw[ZSLOT] = 0.f;
    float lsum = 0.f;
    for (int i = t; i < HW; i += 512) {
        float v = src[i];
        sw[(i >> 6) * PITCH + (i & 63)] = v;
        lsum += v;
    }
#pragma unroll
    for (int o = 16; o; o >>= 1) lsum += __shfl_xor_sync(~0u, lsum, o);
    if ((t & 31) == 0) sred[t >> 5] = lsum;
    __syncthreads();
    if (t == 0) {
        float b = 0.f;
#pragma unroll
        for (int k = 0; k < 16; k++) b += sred[k];
        sbound = 0.05f * b;
    }
    __syncthreads();
    float bound = sbound;

    int w = t >> 5;
    int lane = t & 31;
    int p = (pg << 4) + w;
    int row = p >> 6;
    int col = p & 63;
    int pbase = row * PITCH + col;
    unsigned pb = ((unsigned)row << 8) | (unsigned)col;

    float cum = 0.f;   // warp-uniform running weight sum
    float accL = 0.f;  // per-lane distributed d^2*w accumulator

    const uint4* tp = (const uint4*)g_tab;  // uint4 = 2 entries
    uint4 c0 = __ldg(tp + lane);            // entries 2l, 2l+1
    uint4 c1 = __ldg(tp + 32 + lane);       // entries 64+2l, 64+2l+1

    for (int base = 0; base < NPAD; base += 128) {
        int nb = (base + 128 < NPAD) ? ((base + 128) >> 1) : 0;
        uint4 n0 = __ldg(tp + nb + lane);
        uint4 n1 = __ldg(tp + nb + 32 + lane);

        // SWAR validity: S = word0 + pb; valid <=> (S & 0xC0C0) == 0x4040
        unsigned sA = c0.x + pb;
        int iA = ((sA & 0xC0C0u) == 0x4040u) ? pbase + ((int)c0.x >> 16) : ZSLOT;
        float wA = sw[iA], dA = __uint_as_float(c0.y);
        unsigned sB = c0.z + pb;
        int iB = ((sB & 0xC0C0u) == 0x4040u) ? pbase + ((int)c0.z >> 16) : ZSLOT;
        float wB = sw[iB], dB = __uint_as_float(c0.w);
        unsigned sC = c1.x + pb;
        int iC = ((sC & 0xC0C0u) == 0x4040u) ? pbase + ((int)c1.x >> 16) : ZSLOT;
        float wC = sw[iC], dC = __uint_as_float(c1.y);
        unsigned sD = c1.z + pb;
        int iD = ((sD & 0xC0C0u) == 0x4040u) ? pbase + ((int)c1.z >> 16) : ZSLOT;
        float wD = sw[iD], dD = __uint_as_float(c1.w);

        float p0 = wA + wB, p1 = wC + wD;
        float tot = p0 + p1;  // butterfly reduce (all lanes get total)
#pragma unroll
        for (int o = 1; o < 32; o <<= 1) tot += __shfl_xor_sync(~0u, tot, o);

        if (cum + tot >= bound) {  // warp-uniform crossing test
            // ordered resolve (rare: once per point)
            float s0 = p0;
#pragma unroll
            for (int o = 1; o < 32; o <<= 1) {
                float u = __shfl_up_sync(~0u, s0, o);
                if (lane >= o) s0 += u;
            }
            float totA = __shfl_sync(~0u, s0, 31);
            float s1 = p1;
#pragma unroll
            for (int o = 1; o < 32; o <<= 1) {
                float u = __shfl_up_sync(~0u, s1, o);
                if (lane >= o) s1 += u;
            }
            float bA = cum + (s0 - p0);         // weight before entry A
            float bC = cum + totA + (s1 - p1);  // weight before entry C
            bool fA = bA + wA >= bound;
            bool fB = bA + wA + wB >= bound;
            bool fC = bC + wC >= bound;
            bool fD = bC + wC + wD >= bound;
            unsigned mAB = __ballot_sync(~0u, fA | fB);
            unsigned mCD = __ballot_sync(~0u, fC | fD);
            int crossed = 0;
            if (mAB) {
                int fl = __ffs(mAB) - 1;
                if (lane < fl) accL += dA * wA + dB * wB;
                else if (lane == fl)
                    accL += fA ? dA * (bound - bA)
                               : dA * wA + dB * (bound - (bA + wA));
                crossed = 1;
            } else if (mCD) {
                int fl = __ffs(mCD) - 1;
                accL += dA * wA + dB * wB;  // all of region A precedes
                if (lane < fl) accL += dC * wC + dD * wD;
                else if (lane == fl)
                    accL += fC ? dC * (bound - bC)
                               : dC * wC + dD * (bound - (bC + wC));
                crossed = 1;
            }
            if (crossed) break;  // warp-uniform
            // rounding edge: group said cross but no entry did — continue
        }
        cum += tot;
        accL += dA * wA + dB * wB;
        accL += dC * wC + dD * wD;
        c0 = n0;
        c1 = n1;
    }

#pragma unroll
    for (int o = 16; o; o >>= 1) accL += __shfl_xor_sync(~0u, accL, o);
    if (lane == 0) out[slice * HW + p] = sqrtf(accL / bound);
}

extern "C" void kernel_launch(void* const* d_in, const int* in_sizes, int n_in,
                              void* d_out, int out_size) {
    const float* x = (const float*)d_in[0];
    float* out = (float*)d_out;

    k_build<<<(NPAD + 255) / 256, 256>>>();
    k_main<<<NSLICE * 256, 512>>>(x, out);
}

// round 5
// speedup vs baseline: 1.5171x; 1.5171x over previous
#include <cuda_runtime.h>

// DTM (distance-to-measure) on a 64x64 integer grid.
// Per (b,c) slice: bound = 0.05 * sum(w). Per point p: walk grid points in
// order of increasing squared distance, accumulate weight until crossing
// bound, output sqrt((sum_{d<d*} d^2 w + d*^2 (bound - cum_before)) / bound).
// Weights are quantized to 2^-18 (exactly-perturbed problem; result is
// scale-invariant in w, so rel error ~2^-18 << 1e-3 tolerance). Crossing
// detection runs on exact integer sums via REDUX; value resolution uses the
// float images of the quantized weights.

#define HW 4096
#define NSLICE 12
#define NOFF 16129            // (dy,dx) in [-63,63]^2
#define NPAD 16256            // multiple of 128 (127 batches)
#define PITCH 65
#define ZSLOT (64 * PITCH)    // guaranteed-zero slot for OOB entries
#define QSCALE 262144.0f      // 2^18

// entry: .x = (dy*65+dx)<<16 | (dy+64)<<8 | (dx+64);  .y = float(d2) bits
__device__ __align__(16) uint2 g_tab[NPAD];

// ---- build: 4 lanes per offset compute its sorted rank in closed form ----

__global__ void __launch_bounds__(256) k_build() {
    int gid = blockIdx.x * 256 + threadIdx.x;  // grid sized so gid < 4*NPAD
    int i = gid >> 2;
    int q = gid & 3;
    int dy = i / 127 - 63;
    int dx = i % 127 - 63;
    int d2 = dy * dy + dx * dx;
    int pos = 0;
    if (i < NOFF) {
        for (int a = q; a <= 63; a += 4) {  // +-a handled together
            int na = d2 - a * a;
            if (na < 0) break;
            int s = (int)sqrtf((float)na);  // exact floor at these magnitudes
            bool perf = (s * s == na);
            if (na > 0) {                   // # of b with b^2 < na, |b|<=63
                int tt = perf ? s - 1 : s;
                if (tt > 63) tt = 63;
                int cb = 2 * tt + 1;
                pos += (a == 0) ? cb : 2 * cb;
            }
            if (perf && s <= 63) {          // ties b = +-s, lex (a,b) order
                if (a < dy) pos += (s == 0) ? 1 : 2;
                else if (a == dy) {
                    if (-s < dx) pos++;
                    if (s != 0 && s < dx) pos++;
                }
                if (a != 0) {
                    int aa = -a;
                    if (aa < dy) pos += (s == 0) ? 1 : 2;
                    else if (aa == dy) {
                        if (-s < dx) pos++;
                        if (s != 0 && s < dx) pos++;
                    }
                }
            }
        }
    }
    pos += __shfl_xor_sync(~0u, pos, 1);
    pos += __shfl_xor_sync(~0u, pos, 2);
    if (q == 0) {
        if (i >= NOFF) {
            g_tab[i] = make_uint2(0u, 0u);  // pad: fails SWAR validity
        } else {
            int off = dy * PITCH + dx;
            unsigned vp = ((unsigned)(dy + 64) << 8) | (unsigned)(dx + 64);
            g_tab[pos] = make_uint2(((unsigned)(off & 0xFFFF) << 16) | vp,
                                    __float_as_uint((float)d2));
        }
    }
}

// ---- main: one warp per point, 128 sorted entries per step (4/lane) ----

__global__ void __launch_bounds__(512, 3)
k_main(const float* __restrict__ x, float* __restrict__ out) {
    __shared__ int swq[ZSLOT + 1];
    __shared__ int sredi[16];
    __shared__ float sboundf;
    __shared__ int sboundi;

    int t = threadIdx.x;
    int slice = blockIdx.x >> 8;   // 256 point-groups of 16 per slice
    int pg = blockIdx.x & 255;
    const float4* src4 = (const float4*)(x + slice * HW);

    if (t == 0) swq[ZSLOT] = 0;
    // 8 contiguous cells per thread (never crosses a row)
    float4 v0 = src4[t * 2];
    float4 v1 = src4[t * 2 + 1];
    int cb = t * 8;
    int rb = (cb >> 6) * PITCH + (cb & 63);
    int q0 = (int)(v0.x * QSCALE), q1 = (int)(v0.y * QSCALE);
    int q2 = (int)(v0.z * QSCALE), q3 = (int)(v0.w * QSCALE);
    int q4 = (int)(v1.x * QSCALE), q5 = (int)(v1.y * QSCALE);
    int q6 = (int)(v1.z * QSCALE), q7 = (int)(v1.w * QSCALE);
    swq[rb + 0] = q0; swq[rb + 1] = q1; swq[rb + 2] = q2; swq[rb + 3] = q3;
    swq[rb + 4] = q4; swq[rb + 5] = q5; swq[rb + 6] = q6; swq[rb + 7] = q7;
    int ls = ((q0 + q1) + (q2 + q3)) + ((q4 + q5) + (q6 + q7));
#pragma unroll
    for (int o = 16; o; o >>= 1) ls += __shfl_xor_sync(~0u, ls, o);
    if ((t & 31) == 0) sredi[t >> 5] = ls;
    __syncthreads();
    if (t == 0) {
        int S = 0;
#pragma unroll
        for (int k = 0; k < 16; k++) S += sredi[k];
        float bf = 0.05f * (float)S;
        sboundf = bf;
        sboundi = (int)bf - 4096;  // slack: int test fires <= float crossing
    }
    __syncthreads();
    float bound = sboundf;
    int bound_i = sboundi;

    int w = t >> 5;
    int lane = t & 31;
    int p = (pg << 4) + w;
    int row = p >> 6;
    int col = p & 63;
    int pbase = row * PITCH + col;
    unsigned pb = ((unsigned)row << 8) | (unsigned)col;

    int cum_i = 0;                  // warp-uniform integer running sum
    float cumfL = 0.f;              // per-lane distributed float running sum
    float acc0 = 0.f, acc1 = 0.f;   // per-lane distributed d^2*w accumulators

    const uint4* tp = (const uint4*)g_tab;  // uint4 = 2 entries

    for (int base = 0; base < NPAD; base += 128) {
        uint4 c0 = __ldg(tp + (base >> 1) + lane);        // entries A, B
        uint4 c1 = __ldg(tp + (base >> 1) + 32 + lane);   // entries C, D

        // SWAR validity: S = word0 + pb; valid <=> (S & 0xC0C0) == 0x4040
        unsigned sA = c0.x + pb;
        int iA = ((sA & 0xC0C0u) == 0x4040u) ? pbase + ((int)c0.x >> 16) : ZSLOT;
        int qA = swq[iA];
        float wA = (float)qA, dA = __uint_as_float(c0.y);
        unsigned sB = c0.z + pb;
        int iB = ((sB & 0xC0C0u) == 0x4040u) ? pbase + ((int)c0.z >> 16) : ZSLOT;
        int qB = swq[iB];
        float wB = (float)qB, dB = __uint_as_float(c0.w);
        unsigned sC = c1.x + pb;
        int iC = ((sC & 0xC0C0u) == 0x4040u) ? pbase + ((int)c1.x >> 16) : ZSLOT;
        int qC = swq[iC];
        float wC = (float)qC, dC = __uint_as_float(c1.y);
        unsigned sD = c1.z + pb;
        int iD = ((sD & 0xC0C0u) == 0x4040u) ? pbase + ((int)c1.z >> 16) : ZSLOT;
        int qD = swq[iD];
        float wD = (float)qD, dD = __uint_as_float(c1.w);

        int mi = (qA + qB) + (qC + qD);
        int tot_i = __reduce_add_sync(~0u, mi);   // single-instr warp reduce

        float p0 = wA + wB, p1 = wC + wD;

        if (cum_i + tot_i >= bound_i) {  // warp-uniform, fires <= float cross
            // resolve (rare): reconstruct float cum, ordered scans
            float cumf = cumfL;
#pragma unroll
            for (int o = 1; o < 32; o <<= 1)
                cumf += __shfl_xor_sync(~0u, cumf, o);
            float s0 = p0;
#pragma unroll
            for (int o = 1; o < 32; o <<= 1) {
                float u = __shfl_up_sync(~0u, s0, o);
                if (lane >= o) s0 += u;
            }
            float totA = __shfl_sync(~0u, s0, 31);
            float s1 = p1;
#pragma unroll
            for (int o = 1; o < 32; o <<= 1) {
                float u = __shfl_up_sync(~0u, s1, o);
                if (lane >= o) s1 += u;
            }
            float bA = cumf + (s0 - p0);          // weight before entry A
            float bC = cumf + totA + (s1 - p1);   // weight before entry C
            bool fA = bA + wA >= bound;
            bool fB = bA + wA + wB >= bound;
            bool fC = bC + wC >= bound;
            bool fD = bC + wC + wD >= bound;
            unsigned mAB = __ballot_sync(~0u, fA | fB);
            unsigned mCD = __ballot_sync(~0u, fC | fD);
            int crossed = 0;
            if (mAB) {
                int fl = __ffs(mAB) - 1;
                if (lane < fl) acc0 += dA * wA + dB * wB;
                else if (lane == fl)
                    acc0 += fA ? dA * (bound - bA)
                               : dA * wA + dB * (bound - (bA + wA));
                crossed = 1;
            } else if (mCD) {
                int fl = __ffs(mCD) - 1;
                acc0 += dA * wA + dB * wB;  // all of segment A precedes
                if (lane < fl) acc1 += dC * wC + dD * wD;
                else if (lane == fl)
                    acc1 += fC ? dC * (bound - bC)
                               : dC * wC + dD * (bound - (bC + wC));
                crossed = 1;
            }
            if (crossed) break;  // warp-uniform exit
            // int fired early (slack/rounding) — keep scanning
        }
        cum_i += tot_i;
        cumfL += p0 + p1;
        acc0 += dA * wA + dB * wB;
        acc1 += dC * wC + dD * wD;
    }

    float accL = acc0 + acc1;
#pragma unroll
    for (int o = 16; o; o >>= 1) accL += __shfl_xor_sync(~0u, accL, o);
    if (lane == 0) out[slice * HW + p] = sqrtf(accL / bound);
}

extern "C" void kernel_launch(void* const* d_in, const int* in_sizes, int n_in,
                              void* d_out, int out_size) {
    const float* x = (const float*)d_in[0];
    float* out = (float*)d_out;

    k_build<<<(NPAD * 4) / 256, 256>>>();
    k_main<<<NSLICE * 256, 512>>>(x, out);
}